// round 14
// baseline (speedup 1.0000x reference)
#include <cuda_runtime.h>
#include <math.h>

// ---------------------------------------------------------------------------
// ContrastiveEnergyLearning — Round 14: energyT re-tiled to 64-row CTAs with
// single-buffered weights (103KB smem -> 2 CTAs/SM, 4 warps/SMSP) to lift the
// tensor pipe from 36% toward ~70%. Numerics identical to R13 (tf32 MMA,
// scale-aware flag + subset exact fixup).
// ---------------------------------------------------------------------------

#define NB 32768
#define RTOT (NB * 17)            // 557056
#define NBLK (RTOT / 64)          // 8704
#define TEMP_INV (1.0f / 0.07f)
#define FIXGRID 2048

__device__ float g_A[NB * 256];
__device__ float g_energy[RTOT];
__device__ float g_part[128][4];
__device__ int   g_cnt;
__device__ int   g_list[NB];
__device__ int   g_accov[NB];     // -1 = use approx; 0/1 = exact indicator

// tf32-rounded fp32 weights, K=32 chunks, rows padded to 36 floats (144B)
__device__ float g_W1x[8 * 256 * 36];
__device__ float g_W1y[8 * 256 * 36];
__device__ float g_W2[8 * 128 * 36];
__device__ float g_W3[4 * 64 * 36];

typedef unsigned int u32;

// ---------------- helpers ---------------------------------------------------
__device__ __forceinline__ float gelu_exact(float x) {
    return 0.5f * x * (1.0f + erff(x * 0.7071067811865476f));
}
__device__ __forceinline__ float tf32r(float x) {
    u32 u; asm("cvt.rna.tf32.f32 %0,%1;" : "=r"(u) : "f"(x));
    return __uint_as_float(u);
}
__device__ __forceinline__ u32 smem_u32(const void* p) {
    u32 a;
    asm("{ .reg .u64 t; cvta.to.shared.u64 t, %1; cvt.u32.u64 %0, t; }"
        : "=r"(a) : "l"(p));
    return a;
}
__device__ __forceinline__ void ldsm4(u32& r0, u32& r1, u32& r2, u32& r3, u32 a) {
    asm volatile("ldmatrix.sync.aligned.m8n8.x4.shared.b16 {%0,%1,%2,%3},[%4];"
                 : "=r"(r0), "=r"(r1), "=r"(r2), "=r"(r3) : "r"(a));
}
__device__ __forceinline__ void mma_tf32(float d[4], const u32 a[4], u32 b0, u32 b1) {
    asm volatile("mma.sync.aligned.m16n8k8.row.col.f32.tf32.tf32.f32 "
                 "{%0,%1,%2,%3},{%4,%5,%6,%7},{%8,%9},{%0,%1,%2,%3};"
                 : "+f"(d[0]), "+f"(d[1]), "+f"(d[2]), "+f"(d[3])
                 : "r"(a[0]), "r"(a[1]), "r"(a[2]), "r"(a[3]), "r"(b0), "r"(b1));
}
__device__ __forceinline__ void cpa16(u32 dst, const void* src) {
    asm volatile("cp.async.cg.shared.global [%0],[%1],16;" :: "r"(dst), "l"(src));
}
#define CP_COMMIT() asm volatile("cp.async.commit_group;" ::: "memory")
#define CP_WAIT0()  asm volatile("cp.async.wait_group 0;" ::: "memory")

// ---------------- SMEM layouts (bytes) ---------------------------------------
// mmaA (128-row, 1 CTA/SM — unchanged from R13):
#define XOFF   0u
#define XP     1040u
#define WB0    133120u
#define WB1    169984u
#define SMEM_A 206848
// energyT (64-row, 2 CTAs/SM):
//   X/H1: 64 x 1040B @0 (66560). Weights single-buf @66560 (36864).
//   After L2: H2 @0 (64x528=33792), H3 @33792 (64x68 f32 = 17408), W4 @51200.
#define E_XOFF  0u
#define E_XP    1040u
#define E_WOFF  66560u
#define E_H2OFF 0u
#define E_H2P   528u
#define E_H3OFF 33792u
#define E_W4OFF 51200u
#define SMEM_EN 103424

// ---------------------------------------------------------------------------
// prep: tf32-round weights into [chunk32][out][36] pitch-144B tiles
// ---------------------------------------------------------------------------
__global__ void prepW_a(const float* __restrict__ W1) {
    int i = blockIdx.x * 256 + threadIdx.x;          // 131072 items
    if (i == 0) g_cnt = 0;
    if (i >= 131072) return;
    int half = i >> 16;
    int j = i & 65535;
    int o = j >> 8, k = j & 255;
    float w = W1[o * 512 + half * 256 + k];
    float* dst = half ? g_W1y : g_W1x;
    dst[((k >> 5) * 256 + o) * 36 + (k & 31)] = tf32r(w);
}

__global__ void prepW_b(const float* __restrict__ W2, const float* __restrict__ W3) {
    int i = blockIdx.x * 256 + threadIdx.x;          // 40960 items
    if (i < 32768) {
        int o = i >> 8, k = i & 255;
        g_W2[((k >> 5) * 128 + o) * 36 + (k & 31)] = tf32r(W2[o * 256 + k]);
    } else if (i < 40960) {
        int j = i - 32768;
        int o = j >> 7, k = j & 127;
        g_W3[((k >> 5) * 64 + o) * 36 + (k & 31)] = tf32r(W3[o * 128 + k]);
    }
}

// ---------------- cp.async chunk issue ---------------------------------------
__device__ __forceinline__ void issue_chunk(u32 sb, u32 buf, const void* g,
                                            int bytes, int tid) {
    const unsigned char* gp = (const unsigned char*)g;
    for (int i = tid * 16; i < bytes; i += 4096) cpa16(sb + buf + i, gp + i);
    CP_COMMIT();
}

// ---------------------------------------------------------------------------
// kstep16: one K=16(f32) step (2x m16n8k8 per n-tile)
// ---------------------------------------------------------------------------
template <int MT, int NT>
__device__ __forceinline__ void kstep16(u32 aBase, u32 AP, u32 bBase, u32 WP,
                                        int arow, int nbase, int brow,
                                        float acc[MT][NT][4]) {
    u32 a1[MT][4], a2[MT][4];
    #pragma unroll
    for (int mt = 0; mt < MT; mt++) {
        u32 ad = aBase + (u32)(arow + mt * 16) * AP;
        ldsm4(a1[mt][0], a1[mt][1], a1[mt][2], a1[mt][3], ad);
        ldsm4(a2[mt][0], a2[mt][1], a2[mt][2], a2[mt][3], ad + 32);
    }
    #pragma unroll
    for (int nt = 0; nt < NT; nt++) {
        u32 b0, b1, b2, b3;
        ldsm4(b0, b1, b2, b3, bBase + (u32)(nbase + nt * 8 + brow) * WP);
        #pragma unroll
        for (int mt = 0; mt < MT; mt++) {
            mma_tf32(acc[mt][nt], a1[mt], b0, b1);
            mma_tf32(acc[mt][nt], a2[mt], b2, b3);
        }
    }
}

// ---------------------------------------------------------------------------
// mmaA: g_A = anchor @ W1x^T + b1 (128 rows/CTA, tf32 — unchanged from R13)
// ---------------------------------------------------------------------------
__global__ void __launch_bounds__(256, 1)
mmaA(const float* __restrict__ anchor, const float* __restrict__ b1) {
    extern __shared__ char smc[];
    const u32 sb = smem_u32(smc);
    const int tid = threadIdx.x, lane = tid & 31, wid = tid >> 5;
    const int r0 = blockIdx.x * 128;
    const int mbase = (wid >> 2) * 64;
    const int nbase = (wid & 3) * 64;
    const int arow = mbase + (lane & 15);
    const int aco = (lane & 16) ? 16 : 0;
    const int bco = (lane & 24) * 2;
    const int brow = lane & 7;

    issue_chunk(sb, WB0, g_W1x, 36864, tid);

    for (int i = tid; i < 128 * 64; i += 256) {
        int row = i >> 6, q = i & 63;
        float4 v = ((const float4*)(anchor + (size_t)(r0 + row) * 256))[q];
        float4 t = {tf32r(v.x), tf32r(v.y), tf32r(v.z), tf32r(v.w)};
        *(float4*)(smc + XOFF + (u32)row * XP + q * 16) = t;
    }

    float acc[4][8][4];
    #pragma unroll
    for (int mt = 0; mt < 4; mt++)
        #pragma unroll
        for (int nt = 0; nt < 8; nt++)
            #pragma unroll
            for (int q = 0; q < 4; q++) acc[mt][nt][q] = 0.f;

    for (int c = 0; c < 8; c++) {
        const u32 wb = (c & 1) ? WB1 : WB0;
        CP_WAIT0();
        __syncthreads();
        if (c < 7)
            issue_chunk(sb, (c & 1) ? WB0 : WB1,
                        (const char*)g_W1x + (c + 1) * 36864, 36864, tid);
        #pragma unroll
        for (int kk = 0; kk < 32; kk += 16)
            kstep16<4, 8>(sb + XOFF + (u32)(c * 32 + kk) * 4 + aco, XP,
                          sb + wb + (u32)kk * 4 + bco, 144,
                          arow, nbase, brow, acc);
    }

    const int row0 = mbase + (lane >> 2);
    const int col0 = nbase + (lane & 3) * 2;
    #pragma unroll
    for (int mt = 0; mt < 4; mt++)
        #pragma unroll
        for (int nt = 0; nt < 8; nt++) {
            int col = col0 + nt * 8;
            float2 bb = *(const float2*)(b1 + col);
            #pragma unroll
            for (int h = 0; h < 2; h++) {
                int rr = row0 + mt * 16 + h * 8;
                float2 v = {acc[mt][nt][2 * h] + bb.x, acc[mt][nt][2 * h + 1] + bb.y};
                *(float2*)(g_A + (size_t)(r0 + rr) * 256 + col) = v;
            }
        }
}

// ---------------------------------------------------------------------------
// energyT: fused 4-layer MLP, 64 rows/CTA, 2 CTAs/SM, single-buffered weights
// ---------------------------------------------------------------------------
__global__ void __launch_bounds__(256, 2)
energyT(const float* __restrict__ positive, const float* __restrict__ negatives,
        const float* __restrict__ b2, const float* __restrict__ b3,
        const float* __restrict__ W4, const float* __restrict__ b4) {
    extern __shared__ char smc[];
    const u32 sb = smem_u32(smc);
    const int tid = threadIdx.x, lane = tid & 31, wid = tid >> 5;
    const int r0 = blockIdx.x * 64;
    const int mbase = (wid >> 2) * 32;
    const int row0 = mbase + (lane >> 2);
    const int col0 = (lane & 3) * 2;
    const int arow = mbase + (lane & 15);
    const int aco = (lane & 16) ? 16 : 0;
    const int bco = (lane & 24) * 2;
    const int brow = lane & 7;

    // stage Y tile (tf32-rounded)
    for (int i = tid; i < 64 * 64; i += 256) {
        int row = i >> 6, q = i & 63;
        int g = r0 + row, b = g / 17, j = g - b * 17;
        const float* src = j ? negatives + ((size_t)(b * 16 + j - 1)) * 256
                             : positive + (size_t)b * 256;
        float4 v = ((const float4*)src)[q];
        float4 t = {tf32r(v.x), tf32r(v.y), tf32r(v.z), tf32r(v.w)};
        *(float4*)(smc + E_XOFF + (u32)row * E_XP + q * 16) = t;
    }

    // ================= Layer 1: 64x256, K=256, single-buffered ==============
    {
        const int nbase = (wid & 3) * 64;
        float acc[2][8][4];
        #pragma unroll
        for (int mt = 0; mt < 2; mt++)
            #pragma unroll
            for (int nt = 0; nt < 8; nt++)
                #pragma unroll
                for (int q = 0; q < 4; q++) acc[mt][nt][q] = 0.f;

        for (int c = 0; c < 8; c++) {
            __syncthreads();   // prior chunk reads done (c0: Y staging done)
            issue_chunk(sb, E_WOFF, (const char*)g_W1y + c * 36864, 36864, tid);
            CP_WAIT0();
            __syncthreads();
            #pragma unroll
            for (int kk = 0; kk < 32; kk += 16)
                kstep16<2, 8>(sb + E_XOFF + (u32)(c * 32 + kk) * 4 + aco, E_XP,
                              sb + E_WOFF + (u32)kk * 4 + bco, 144,
                              arow, nbase, brow, acc);
        }
        __syncthreads();   // all X reads done; X region becomes H1
        #pragma unroll
        for (int mt = 0; mt < 2; mt++)
            #pragma unroll
            for (int nt = 0; nt < 8; nt++) {
                int col = nbase + nt * 8 + col0;
                #pragma unroll
                for (int h = 0; h < 2; h++) {
                    int rr = row0 + mt * 16 + h * 8;
                    int gb = (r0 + rr) / 17;
                    float2 a = *(const float2*)(g_A + (size_t)gb * 256 + col);
                    float2 v = {tf32r(gelu_exact(acc[mt][nt][2 * h] + a.x)),
                                tf32r(gelu_exact(acc[mt][nt][2 * h + 1] + a.y))};
                    *(float2*)(smc + E_XOFF + (u32)rr * E_XP + col * 4) = v;
                }
            }
    }

    // ================= Layer 2: 64x128, K=256, single-buffered ==============
    {
        const int nbase = (wid & 3) * 32;
        float acc[2][4][4];
        #pragma unroll
        for (int mt = 0; mt < 2; mt++)
            #pragma unroll
            for (int nt = 0; nt < 4; nt++)
                #pragma unroll
                for (int q = 0; q < 4; q++) acc[mt][nt][q] = 0.f;

        for (int c = 0; c < 8; c++) {
            __syncthreads();   // prior reads done (c0: H1 stores done)
            issue_chunk(sb, E_WOFF, (const char*)g_W2 + c * 18432, 18432, tid);
            CP_WAIT0();
            __syncthreads();
            #pragma unroll
            for (int kk = 0; kk < 32; kk += 16)
                kstep16<2, 4>(sb + E_XOFF + (u32)(c * 32 + kk) * 4 + aco, E_XP,
                              sb + E_WOFF + (u32)kk * 4 + bco, 144,
                              arow, nbase, brow, acc);
        }
        __syncthreads();   // H1 reads done; front of X region becomes H2
        #pragma unroll
        for (int mt = 0; mt < 2; mt++)
            #pragma unroll
            for (int nt = 0; nt < 4; nt++) {
                int col = nbase + nt * 8 + col0;
                float2 bb = *(const float2*)(b2 + col);
                #pragma unroll
                for (int h = 0; h < 2; h++) {
                    int rr = row0 + mt * 16 + h * 8;
                    float2 v = {tf32r(gelu_exact(acc[mt][nt][2 * h] + bb.x)),
                                tf32r(gelu_exact(acc[mt][nt][2 * h + 1] + bb.y))};
                    *(float2*)(smc + E_H2OFF + (u32)rr * E_H2P + col * 4) = v;
                }
            }
        if (tid < 64) ((float*)(smc + E_W4OFF))[tid] = W4[tid];
    }

    // ================= Layer 3: 64x64, K=128, single-buffered ===============
    {
        const int nbase = (wid & 3) * 16;
        float acc[2][2][4];
        #pragma unroll
        for (int mt = 0; mt < 2; mt++)
            #pragma unroll
            for (int nt = 0; nt < 2; nt++)
                #pragma unroll
                for (int q = 0; q < 4; q++) acc[mt][nt][q] = 0.f;

        for (int c = 0; c < 4; c++) {
            __syncthreads();   // prior reads done (c0: H2 + W4 stores done)
            issue_chunk(sb, E_WOFF, (const char*)g_W3 + c * 9216, 9216, tid);
            CP_WAIT0();
            __syncthreads();
            #pragma unroll
            for (int kk = 0; kk < 32; kk += 16)
                kstep16<2, 2>(sb + E_H2OFF + (u32)(c * 32 + kk) * 4 + aco, E_H2P,
                              sb + E_WOFF + (u32)kk * 4 + bco, 144,
                              arow, nbase, brow, acc);
        }
        // epilogue -> H3 fp32 (disjoint from H2)
        float* H3 = (float*)(smc + E_H3OFF);
        #pragma unroll
        for (int mt = 0; mt < 2; mt++)
            #pragma unroll
            for (int nt = 0; nt < 2; nt++) {
                int col = nbase + nt * 8 + col0;
                float2 bb = *(const float2*)(b3 + col);
                #pragma unroll
                for (int h = 0; h < 2; h++) {
                    int rr = row0 + mt * 16 + h * 8;
                    float2 v = {gelu_exact(acc[mt][nt][2 * h] + bb.x),
                                gelu_exact(acc[mt][nt][2 * h + 1] + bb.y)};
                    *(float2*)(H3 + rr * 68 + col) = v;
                }
            }
    }
    __syncthreads();

    // ================= Layer 4: dot(64) =====================================
    if (tid < 64) {
        const float* H3 = (const float*)(smc + E_H3OFF);
        const float* w4 = (const float*)(smc + E_W4OFF);
        float e = b4[0];
        #pragma unroll
        for (int k = 0; k < 64; k++) e += H3[tid * 68 + k] * w4[k];
        g_energy[r0 + tid] = e;
    }
}

// ---------------------------------------------------------------------------
// flagK: scale-aware near-tie detection (R10-proven): T = 0.03*(max-min)
// ---------------------------------------------------------------------------
__global__ void flagK() {
    int b = blockIdx.x * 256 + threadIdx.x;
    const float* e = &g_energy[(size_t)b * 17];
    float mx = e[0], mn = e[0], mnn = e[1];
    #pragma unroll
    for (int j = 1; j < 17; j++) {
        mx = fmaxf(mx, e[j]);
        mn = fminf(mn, e[j]);
        if (j >= 2) mnn = fminf(mnn, e[j]);
    }
    float T = 0.03f * (mx - mn);
    g_accov[b] = -1;
    if (fabsf(e[0] - mnn) < T) {
        int p = atomicAdd(&g_cnt, 1);
        g_list[p] = b;
    }
}

// ---------------------------------------------------------------------------
// fixup3: per flagged batch, exact fp32 recompute of e0 and negatives within
// 2T of the approx min; writes accuracy override only.
// ---------------------------------------------------------------------------
__global__ void __launch_bounds__(256)
fixup3(const float* __restrict__ anchor, const float* __restrict__ positive,
       const float* __restrict__ negatives,
       const float* __restrict__ W1, const float* __restrict__ b1,
       const float* __restrict__ W2, const float* __restrict__ b2,
       const float* __restrict__ W3, const float* __restrict__ b3,
       const float* __restrict__ W4, const float* __restrict__ b4) {
    __shared__ float xv[256], yv[256], apart[256], h1[256], h2[128], h3[64];
    __shared__ int   sS[16], nS;
    __shared__ float eres[18];
    const int tid = threadIdx.x, lane = tid & 31, wid = tid >> 5;  // 8 warps
    const int ncase = g_cnt;

    for (int q = blockIdx.x; q < ncase; q += FIXGRID) {
        const int b = g_list[q];
        if (tid == 0) {
            const float* e = &g_energy[(size_t)b * 17];
            float mx = e[0], mn = e[0], mnn = e[1];
            #pragma unroll
            for (int j = 1; j < 17; j++) {
                mx = fmaxf(mx, e[j]);
                mn = fminf(mn, e[j]);
                if (j >= 2) mnn = fminf(mnn, e[j]);
            }
            float T = 0.03f * (mx - mn);
            int n = 0;
            #pragma unroll
            for (int j = 1; j < 17; j++)
                if (e[j] <= mnn + 2.0f * T) sS[n++] = j;
            nS = n;
        }
        xv[tid] = anchor[(size_t)b * 256 + tid];
        __syncthreads();

        for (int o = wid; o < 256; o += 8) {
            const float* w = W1 + (size_t)o * 512;
            float acc = 0.f;
            #pragma unroll
            for (int i = 0; i < 8; i++) acc += w[lane + 32 * i] * xv[lane + 32 * i];
            #pragma unroll
            for (int s = 16; s; s >>= 1) acc += __shfl_xor_sync(0xFFFFFFFFu, acc, s);
            if (lane == 0) apart[o] = acc + b1[o];
        }
        __syncthreads();

        const int ncand = nS + 1;
        for (int s = 0; s < ncand; s++) {
            int j = (s == 0) ? 0 : sS[s - 1];
            const float* ysrc = j ? negatives + ((size_t)(b * 16 + j - 1)) * 256
                                  : positive + (size_t)b * 256;
            yv[tid] = ysrc[tid];
            __syncthreads();

            for (int o = wid; o < 256; o += 8) {
                const float* w = W1 + (size_t)o * 512 + 256;
                float acc = 0.f;
                #pragma unroll
                for (int i = 0; i < 8; i++) acc += w[lane + 32 * i] * yv[lane + 32 * i];
                #pragma unroll
                for (int st = 16; st; st >>= 1) acc += __shfl_xor_sync(0xFFFFFFFFu, acc, st);
                if (lane == 0) h1[o] = gelu_exact(apart[o] + acc);
            }
            __syncthreads();

            for (int o = wid; o < 128; o += 8) {
                const float* w = W2 + (size_t)o * 256;
                float acc = 0.f;
                #pragma unroll
                for (int i = 0; i < 8; i++) acc += w[lane + 32 * i] * h1[lane + 32 * i];
                #pragma unroll
                for (int st = 16; st; st >>= 1) acc += __shfl_xor_sync(0xFFFFFFFFu, acc, st);
                if (lane == 0) h2[o] = gelu_exact(acc + b2[o]);
            }
            __syncthreads();

            for (int o = wid; o < 64; o += 8) {
                const float* w = W3 + (size_t)o * 128;
                float acc = 0.f;
                #pragma unroll
                for (int i = 0; i < 4; i++) acc += w[lane + 32 * i] * h2[lane + 32 * i];
                #pragma unroll
                for (int st = 16; st; st >>= 1) acc += __shfl_xor_sync(0xFFFFFFFFu, acc, st);
                if (lane == 0) h3[o] = gelu_exact(acc + b3[o]) * W4[o];
            }
            __syncthreads();

            if (wid == 0) {
                float acc = h3[lane] + h3[lane + 32];
                #pragma unroll
                for (int st = 16; st; st >>= 1) acc += __shfl_xor_sync(0xFFFFFFFFu, acc, st);
                if (lane == 0) eres[s] = acc + b4[0];
            }
            __syncthreads();
        }

        if (tid == 0) {
            float emin = eres[1];
            for (int s = 2; s < ncand; s++) emin = fminf(emin, eres[s]);
            g_accov[b] = (eres[0] <= emin) ? 1 : 0;
        }
        __syncthreads();
    }
}

// ---------------------------------------------------------------------------
// reductions (reduce1 consumes the accuracy override)
// ---------------------------------------------------------------------------
__global__ void reduce1() {
    __shared__ float sl[256], sp[256], sn[256], sa[256];
    const int t = threadIdx.x;
    const int b = blockIdx.x * 256 + t;
    const float* e = &g_energy[(size_t)b * 17];

    float v[17];
    #pragma unroll
    for (int j = 0; j < 17; j++) v[j] = e[j];

    float l0 = -v[0] * TEMP_INV;
    float mx = l0;
    #pragma unroll
    for (int j = 1; j < 17; j++) mx = fmaxf(mx, -v[j] * TEMP_INV);
    float s = 0.f;
    #pragma unroll
    for (int j = 0; j < 17; j++) s += expf(-v[j] * TEMP_INV - mx);
    float loss = mx + logf(s) - l0;

    float pos = v[0], neg = 0.f, ok = 1.f;
    #pragma unroll
    for (int j = 1; j < 17; j++) {
        neg += v[j];
        if (v[j] < v[0]) ok = 0.f;
    }
    int ov = g_accov[b];
    if (ov >= 0) ok = (float)ov;

    sl[t] = loss; sp[t] = pos; sn[t] = neg; sa[t] = ok;
    __syncthreads();
    for (int st = 128; st > 0; st >>= 1) {
        if (t < st) {
            sl[t] += sl[t + st]; sp[t] += sp[t + st];
            sn[t] += sn[t + st]; sa[t] += sa[t + st];
        }
        __syncthreads();
    }
    if (t == 0) {
        g_part[blockIdx.x][0] = sl[0];
        g_part[blockIdx.x][1] = sp[0];
        g_part[blockIdx.x][2] = sn[0];
        g_part[blockIdx.x][3] = sa[0];
    }
}

__global__ void reduce2(float* __restrict__ out) {
    __shared__ float s[128][4];
    const int t = threadIdx.x;
    #pragma unroll
    for (int c = 0; c < 4; c++) s[t][c] = g_part[t][c];
    __syncthreads();
    for (int st = 64; st > 0; st >>= 1) {
        if (t < st) {
            #pragma unroll
            for (int c = 0; c < 4; c++) s[t][c] += s[t + st][c];
        }
        __syncthreads();
    }
    if (t == 0) {
        out[0] = s[0][0] / 32768.0f;
        out[1] = s[0][1] / 32768.0f;
        out[2] = s[0][2] / (32768.0f * 16.0f);
        out[3] = s[0][3] / 32768.0f;
    }
}

// ---------------------------------------------------------------------------
extern "C" void kernel_launch(void* const* d_in, const int* in_sizes, int n_in,
                              void* d_out, int out_size) {
    const float* anchor    = (const float*)d_in[0];
    const float* positive  = (const float*)d_in[1];
    const float* negatives = (const float*)d_in[2];
    const float* W1 = (const float*)d_in[3];
    const float* b1 = (const float*)d_in[4];
    const float* W2 = (const float*)d_in[5];
    const float* b2 = (const float*)d_in[6];
    const float* W3 = (const float*)d_in[7];
    const float* b3 = (const float*)d_in[8];
    const float* W4 = (const float*)d_in[9];
    const float* b4 = (const float*)d_in[10];
    float* out = (float*)d_out;

    cudaFuncSetAttribute(mmaA,    cudaFuncAttributeMaxDynamicSharedMemorySize, SMEM_A);
    cudaFuncSetAttribute(energyT, cudaFuncAttributeMaxDynamicSharedMemorySize, SMEM_EN);

    prepW_a<<<512, 256>>>(W1);                                      // 1 (zeros g_cnt)
    prepW_b<<<160, 256>>>(W2, W3);                                  // 2
    mmaA<<<NB / 128, 256, SMEM_A>>>(anchor, b1);                    // 3
    energyT<<<NBLK, 256, SMEM_EN>>>(positive, negatives, b2, b3, W4, b4); // 4 (profiled)
    flagK<<<NB / 256, 256>>>();                                     // 5
    fixup3<<<FIXGRID, 256>>>(anchor, positive, negatives,
                             W1, b1, W2, b2, W3, b3, W4, b4);       // 6
    reduce1<<<128, 256>>>();                                        // 7
    reduce2<<<1, 128>>>(out);                                       // 8
}

// round 15
// speedup vs baseline: 1.0754x; 1.0754x over previous
#include <cuda_runtime.h>
#include <cuda_bf16.h>
#include <math.h>

// ---------------------------------------------------------------------------
// ContrastiveEnergyLearning — Round 15: R13 control flow (128-row CTAs, occ1,
// double-buffered weight streaming) with the MMA engine swapped from tf32
// single-pass to 2-term bf16 split (Xh*Wh + Xh*Wl): same MMA instruction
// count at bf16 rt (~6.5 vs 7.5 cyc), 25% fewer ldsm, half the smem bytes.
// Scale-aware flag + subset exact fixup unchanged (handles ~1e-3 energy err).
// ---------------------------------------------------------------------------

#define NB 32768
#define RTOT (NB * 17)            // 557056
#define NBLK (RTOT / 128)         // 4352
#define TEMP_INV (1.0f / 0.07f)
#define FIXGRID 2048

__device__ float g_A[NB * 256];
__device__ float g_energy[RTOT];
__device__ float g_part[128][4];
__device__ int   g_cnt;
__device__ int   g_list[NB];
__device__ int   g_accov[NB];     // -1 = use approx; 0/1 = exact indicator

// prepped bf16 hi/lo weights: [chunk32][out][40 bf16] (pitch 80B) — R9 layout
__device__ unsigned char g_W1xh[163840], g_W1xl[163840];  // 8 x 256 x 80
__device__ unsigned char g_W1yh[163840], g_W1yl[163840];
__device__ unsigned char g_W2h[81920],   g_W2l[81920];    // 8 x 128 x 80
__device__ unsigned char g_W3h[20480],   g_W3l[20480];    // 4 x 64 x 80

typedef unsigned int u32;

// ---------------- helpers ---------------------------------------------------
__device__ __forceinline__ float gelu_exact(float x) {
    return 0.5f * x * (1.0f + erff(x * 0.7071067811865476f));
}
__device__ __forceinline__ u32 bfpair(float a, float b) {
    __nv_bfloat162 t = __floats2bfloat162_rn(a, b);
    return *(u32*)&t;
}
__device__ __forceinline__ u32 smem_u32(const void* p) {
    u32 a;
    asm("{ .reg .u64 t; cvta.to.shared.u64 t, %1; cvt.u32.u64 %0, t; }"
        : "=r"(a) : "l"(p));
    return a;
}
__device__ __forceinline__ void ldsm4(u32& r0, u32& r1, u32& r2, u32& r3, u32 a) {
    asm volatile("ldmatrix.sync.aligned.m8n8.x4.shared.b16 {%0,%1,%2,%3},[%4];"
                 : "=r"(r0), "=r"(r1), "=r"(r2), "=r"(r3) : "r"(a));
}
__device__ __forceinline__ void mma_bf16(float d[4], const u32 a[4], u32 b0, u32 b1) {
    asm volatile("mma.sync.aligned.m16n8k16.row.col.f32.bf16.bf16.f32 "
                 "{%0,%1,%2,%3},{%4,%5,%6,%7},{%8,%9},{%0,%1,%2,%3};"
                 : "+f"(d[0]), "+f"(d[1]), "+f"(d[2]), "+f"(d[3])
                 : "r"(a[0]), "r"(a[1]), "r"(a[2]), "r"(a[3]), "r"(b0), "r"(b1));
}
__device__ __forceinline__ void cpa16(u32 dst, const void* src) {
    asm volatile("cp.async.cg.shared.global [%0],[%1],16;" :: "r"(dst), "l"(src));
}
#define CP_COMMIT() asm volatile("cp.async.commit_group;" ::: "memory")
#define CP_WAIT0()  asm volatile("cp.async.wait_group 0;" ::: "memory")

// ---------------- SMEM layout (bytes) ---------------------------------------
// energyT: X/H1 hi-bf16 128 x 528B @0 (67584).
//   WB0 @67584 (hi 20480 + lo 20480 = 40960), WB1 @108544 -> ends 149504.
//   H2 hi-bf16 @149504, 128 x 272B = 34816 -> ends 184320.
//   H3 f32 @0 (128 x 68 f32, dead H1); W4 @34816 (dead H1).
#define XOFF   0u
#define XP     528u
#define WB0    67584u
#define WB1    108544u
#define H2OFF  149504u
#define H2P    272u
#define H3OFF  0u
#define W4OFF  34816u
#define SMEM_EN 184320
#define SMEM_A  149504

// ---------------------------------------------------------------------------
// prep: split fp32 -> bf16 hi/lo into [chunk32][out][40] pitch-80 tiles (R9)
// ---------------------------------------------------------------------------
__global__ void prepW_a(const float* __restrict__ W1) {
    int i = blockIdx.x * 256 + threadIdx.x;          // 131072 items
    if (i == 0) g_cnt = 0;
    if (i >= 131072) return;
    int half = i >> 16;
    int j = i & 65535;
    int o = j >> 8, k = j & 255;
    float w = W1[o * 512 + half * 256 + k];
    u32 off = ((u32)(k >> 5) * 256 + o) * 80 + (k & 31) * 2;
    __nv_bfloat16 h = __float2bfloat16_rn(w);
    __nv_bfloat16 l = __float2bfloat16_rn(w - __bfloat162float(h));
    unsigned char* dh = half ? g_W1yh : g_W1xh;
    unsigned char* dl = half ? g_W1yl : g_W1xl;
    *(__nv_bfloat16*)(dh + off) = h;
    *(__nv_bfloat16*)(dl + off) = l;
}

__global__ void prepW_b(const float* __restrict__ W2, const float* __restrict__ W3) {
    int i = blockIdx.x * 256 + threadIdx.x;          // 40960 items
    float w; unsigned char *dh, *dl; u32 off;
    if (i < 32768) {
        int o = i >> 8, k = i & 255;
        w = W2[o * 256 + k];
        off = ((u32)(k >> 5) * 128 + o) * 80 + (k & 31) * 2;
        dh = g_W2h; dl = g_W2l;
    } else if (i < 40960) {
        int j = i - 32768;
        int o = j >> 7, k = j & 127;
        w = W3[o * 128 + k];
        off = ((u32)(k >> 5) * 64 + o) * 80 + (k & 31) * 2;
        dh = g_W3h; dl = g_W3l;
    } else return;
    __nv_bfloat16 h = __float2bfloat16_rn(w);
    __nv_bfloat16 l = __float2bfloat16_rn(w - __bfloat162float(h));
    *(__nv_bfloat16*)(dh + off) = h;
    *(__nv_bfloat16*)(dl + off) = l;
}

// ---------------- cp.async chunk issue (hi at buf, lo at buf+hb) -------------
__device__ __forceinline__ void issue_chunk(u32 sb, u32 buf, const unsigned char* gh,
                                            const unsigned char* gl, int hb, int tid) {
    for (int i = tid * 16; i < hb; i += 4096) {
        cpa16(sb + buf + i, gh + i);
        cpa16(sb + buf + hb + i, gl + i);
    }
    CP_COMMIT();
}

// ---------------------------------------------------------------------------
// kstepB: one K=16 step, 2-term bf16 (Xh*Wh + Xh*Wl).
//   A (hi only): ldsm.x4 per m-tile at aBase + row*AP (aBase includes k-byte
//   offset + akof). B: bsel lane trick (lanes<16 read hi buf, >=16 lo buf);
//   one ldsm.x4 per n-tile gives b0,b1 = hi-K16 frags, b2,b3 = lo-K16 frags.
// ---------------------------------------------------------------------------
template <int MT, int NT>
__device__ __forceinline__ void kstepB(u32 aBase, u32 AP, u32 bBase,
                                       int arow, int nbase, int bl8,
                                       float acc[MT][NT][4]) {
    u32 ah[MT][4];
    #pragma unroll
    for (int mt = 0; mt < MT; mt++) {
        u32 ad = aBase + (u32)(arow + mt * 16) * AP;
        ldsm4(ah[mt][0], ah[mt][1], ah[mt][2], ah[mt][3], ad);
    }
    #pragma unroll
    for (int nt = 0; nt < NT; nt++) {
        u32 b0, b1, b2, b3;
        ldsm4(b0, b1, b2, b3, bBase + (u32)(nbase + nt * 8 + bl8) * 80);
        #pragma unroll
        for (int mt = 0; mt < MT; mt++) {
            mma_bf16(acc[mt][nt], ah[mt], b0, b1);   // hi * hi
            mma_bf16(acc[mt][nt], ah[mt], b2, b3);   // hi * lo
        }
    }
}

// ---------------------------------------------------------------------------
// mmaA: g_A = anchor @ W1x^T + b1 (128 rows/CTA, bf16 2-term)
// ---------------------------------------------------------------------------
__global__ void __launch_bounds__(256, 1)
mmaA(const float* __restrict__ anchor, const float* __restrict__ b1) {
    extern __shared__ char smc[];
    const u32 sb = smem_u32(smc);
    const int tid = threadIdx.x, lane = tid & 31, wid = tid >> 5;
    const int r0 = blockIdx.x * 128;
    const int mbase = (wid >> 2) * 64;
    const int nbase = (wid & 3) * 64;
    const int arow = mbase + (lane & 15);
    const u32 akof = (lane & 16) ? 16u : 0u;   // bytes: 8 bf16
    const int bl8 = lane & 7;
    const u32 bk8 = (u32)(lane & 8) * 2;       // bytes
    const u32 bhl = (lane < 16) ? 0u : 20480u; // hi vs lo buffer half

    issue_chunk(sb, WB0, g_W1xh, g_W1xl, 20480, tid);

    for (int i = tid; i < 128 * 64; i += 256) {
        int row = i >> 6, q = i & 63;
        float4 v = ((const float4*)(anchor + (size_t)(r0 + row) * 256))[q];
        uint2 hh = {bfpair(v.x, v.y), bfpair(v.z, v.w)};
        *(uint2*)(smc + XOFF + (u32)row * XP + q * 8) = hh;
    }

    float acc[4][8][4];
    #pragma unroll
    for (int mt = 0; mt < 4; mt++)
        #pragma unroll
        for (int nt = 0; nt < 8; nt++)
            #pragma unroll
            for (int q = 0; q < 4; q++) acc[mt][nt][q] = 0.f;

    for (int c = 0; c < 8; c++) {
        const u32 wb = (c & 1) ? WB1 : WB0;
        CP_WAIT0();
        __syncthreads();
        if (c < 7)
            issue_chunk(sb, (c & 1) ? WB0 : WB1,
                        g_W1xh + (c + 1) * 20480, g_W1xl + (c + 1) * 20480, 20480, tid);
        #pragma unroll
        for (int kk = 0; kk < 32; kk += 16)
            kstepB<4, 8>(sb + XOFF + (u32)(c * 32 + kk) * 2 + akof, XP,
                         sb + wb + bhl + (u32)kk * 2 + bk8,
                         arow, nbase, bl8, acc);
    }

    const int row0 = mbase + (lane >> 2);
    const int col0 = nbase + (lane & 3) * 2;
    #pragma unroll
    for (int mt = 0; mt < 4; mt++)
        #pragma unroll
        for (int nt = 0; nt < 8; nt++) {
            int col = col0 + nt * 8;
            float2 bb = *(const float2*)(b1 + col);
            #pragma unroll
            for (int h = 0; h < 2; h++) {
                int rr = row0 + mt * 16 + h * 8;
                float2 v = {acc[mt][nt][2 * h] + bb.x, acc[mt][nt][2 * h + 1] + bb.y};
                *(float2*)(g_A + (size_t)(r0 + rr) * 256 + col) = v;
            }
        }
}

// ---------------------------------------------------------------------------
// energyT: fused 4-layer MLP, 128 rows/CTA, bf16 2-term, double-buffered
// ---------------------------------------------------------------------------
__global__ void __launch_bounds__(256, 1)
energyT(const float* __restrict__ positive, const float* __restrict__ negatives,
        const float* __restrict__ b2, const float* __restrict__ b3,
        const float* __restrict__ W4, const float* __restrict__ b4) {
    extern __shared__ char smc[];
    const u32 sb = smem_u32(smc);
    const int tid = threadIdx.x, lane = tid & 31, wid = tid >> 5;
    const int r0 = blockIdx.x * 128;
    const int mbase = (wid >> 2) * 64;
    const int row0 = mbase + (lane >> 2);
    const int col0 = (lane & 3) * 2;
    const int arow = mbase + (lane & 15);
    const u32 akof = (lane & 16) ? 16u : 0u;
    const int bl8 = lane & 7;
    const u32 bk8 = (u32)(lane & 8) * 2;
    const u32 bhl = (lane < 16) ? 0u : 20480u;   // L1 buffer half (hb=20480)
    const u32 bhl2 = (lane < 16) ? 0u : 10240u;  // L2 (hb=10240)
    const u32 bhl3 = (lane < 16) ? 0u : 5120u;   // L3 (hb=5120)

    issue_chunk(sb, WB0, g_W1yh, g_W1yl, 20480, tid);

    // stage Y tile (hi bf16 only)
    for (int i = tid; i < 128 * 64; i += 256) {
        int row = i >> 6, q = i & 63;
        int g = r0 + row, b = g / 17, j = g - b * 17;
        const float* src = j ? negatives + ((size_t)(b * 16 + j - 1)) * 256
                             : positive + (size_t)b * 256;
        float4 v = ((const float4*)src)[q];
        uint2 hh = {bfpair(v.x, v.y), bfpair(v.z, v.w)};
        *(uint2*)(smc + XOFF + (u32)row * XP + q * 8) = hh;
    }

    // ================= Layer 1: 128x256, K=256, 8 chunks ====================
    {
        const int nbase = (wid & 3) * 64;
        float acc[4][8][4];
        #pragma unroll
        for (int mt = 0; mt < 4; mt++)
            #pragma unroll
            for (int nt = 0; nt < 8; nt++)
                #pragma unroll
                for (int q = 0; q < 4; q++) acc[mt][nt][q] = 0.f;

        for (int c = 0; c < 8; c++) {
            const u32 wb = (c & 1) ? WB1 : WB0;
            CP_WAIT0();
            __syncthreads();
            if (c < 7)
                issue_chunk(sb, (c & 1) ? WB0 : WB1,
                            g_W1yh + (c + 1) * 20480, g_W1yl + (c + 1) * 20480, 20480, tid);
            else
                issue_chunk(sb, WB0, g_W2h, g_W2l, 10240, tid);   // L2 chunk 0
            #pragma unroll
            for (int kk = 0; kk < 32; kk += 16)
                kstepB<4, 8>(sb + XOFF + (u32)(c * 32 + kk) * 2 + akof, XP,
                             sb + wb + bhl + (u32)kk * 2 + bk8,
                             arow, nbase, bl8, acc);
        }
        __syncthreads();   // all X reads done; X region becomes H1 (in place)
        #pragma unroll
        for (int mt = 0; mt < 4; mt++)
            #pragma unroll
            for (int nt = 0; nt < 8; nt++) {
                int col = nbase + nt * 8 + col0;
                #pragma unroll
                for (int h = 0; h < 2; h++) {
                    int rr = row0 + mt * 16 + h * 8;
                    int gb = (r0 + rr) / 17;
                    float2 a = *(const float2*)(g_A + (size_t)gb * 256 + col);
                    float v0 = gelu_exact(acc[mt][nt][2 * h] + a.x);
                    float v1 = gelu_exact(acc[mt][nt][2 * h + 1] + a.y);
                    *(u32*)(smc + XOFF + (u32)rr * XP + col * 2) = bfpair(v0, v1);
                }
            }
    }

    // ================= Layer 2: 128x128, K=256, 8 chunks ====================
    {
        const int nbase = (wid & 3) * 32;
        float acc[4][4][4];
        #pragma unroll
        for (int mt = 0; mt < 4; mt++)
            #pragma unroll
            for (int nt = 0; nt < 4; nt++)
                #pragma unroll
                for (int q = 0; q < 4; q++) acc[mt][nt][q] = 0.f;

        for (int c = 0; c < 8; c++) {
            const u32 wb = (c & 1) ? WB1 : WB0;
            CP_WAIT0();
            __syncthreads();   // chunk c present; (c==0: H1 stores published)
            if (c < 7)
                issue_chunk(sb, (c & 1) ? WB0 : WB1,
                            g_W2h + (c + 1) * 10240, g_W2l + (c + 1) * 10240, 10240, tid);
            else
                issue_chunk(sb, WB0, g_W3h, g_W3l, 5120, tid);    // L3 chunk 0
            #pragma unroll
            for (int kk = 0; kk < 32; kk += 16)
                kstepB<4, 4>(sb + XOFF + (u32)(c * 32 + kk) * 2 + akof, XP,
                             sb + wb + bhl2 + (u32)kk * 2 + bk8,
                             arow, nbase, bl8, acc);
        }
        __syncthreads();   // H1/chunk reads done; write H2 (separate region)
        #pragma unroll
        for (int mt = 0; mt < 4; mt++)
            #pragma unroll
            for (int nt = 0; nt < 4; nt++) {
                int col = nbase + nt * 8 + col0;
                float2 bb = *(const float2*)(b2 + col);
                #pragma unroll
                for (int h = 0; h < 2; h++) {
                    int rr = row0 + mt * 16 + h * 8;
                    float v0 = gelu_exact(acc[mt][nt][2 * h] + bb.x);
                    float v1 = gelu_exact(acc[mt][nt][2 * h + 1] + bb.y);
                    *(u32*)(smc + H2OFF + (u32)rr * H2P + col * 2) = bfpair(v0, v1);
                }
            }
        if (tid < 64) ((float*)(smc + W4OFF))[tid] = W4[tid];
    }

    // ================= Layer 3: 128x64, K=128, 4 chunks =====================
    {
        const int nbase = (wid & 3) * 16;
        float acc[4][2][4];
        #pragma unroll
        for (int mt = 0; mt < 4; mt++)
            #pragma unroll
            for (int nt = 0; nt < 2; nt++)
                #pragma unroll
                for (int q = 0; q < 4; q++) acc[mt][nt][q] = 0.f;

        for (int c = 0; c < 4; c++) {
            const u32 wb = (c & 1) ? WB1 : WB0;
            CP_WAIT0();
            __syncthreads();   // chunk present; (c==0: H2 + W4 published)
            if (c < 3)
                issue_chunk(sb, (c & 1) ? WB0 : WB1,
                            g_W3h + (c + 1) * 5120, g_W3l + (c + 1) * 5120, 5120, tid);
            #pragma unroll
            for (int kk = 0; kk < 32; kk += 16)
                kstepB<4, 2>(sb + H2OFF + (u32)(c * 32 + kk) * 2 + akof, H2P,
                             sb + wb + bhl3 + (u32)kk * 2 + bk8,
                             arow, nbase, bl8, acc);
        }
        // epilogue -> H3 fp32 in dead H1 region
        float* H3 = (float*)(smc + H3OFF);
        #pragma unroll
        for (int mt = 0; mt < 4; mt++)
            #pragma unroll
            for (int nt = 0; nt < 2; nt++) {
                int col = nbase + nt * 8 + col0;
                float2 bb = *(const float2*)(b3 + col);
                #pragma unroll
                for (int h = 0; h < 2; h++) {
                    int rr = row0 + mt * 16 + h * 8;
                    float2 v = {gelu_exact(acc[mt][nt][2 * h] + bb.x),
                                gelu_exact(acc[mt][nt][2 * h + 1] + bb.y)};
                    *(float2*)(H3 + rr * 68 + col) = v;
                }
            }
    }
    __syncthreads();

    // ================= Layer 4: dot(64) =====================================
    if (tid < 128) {
        const float* H3 = (const float*)(smc + H3OFF);
        const float* w4 = (const float*)(smc + W4OFF);
        float e = b4[0];
        #pragma unroll
        for (int k = 0; k < 64; k++) e += H3[tid * 68 + k] * w4[k];
        g_energy[r0 + tid] = e;
    }
}

// ---------------------------------------------------------------------------
// flagK: scale-aware near-tie detection (R10/R13-proven): T = 0.03*(max-min)
// ---------------------------------------------------------------------------
__global__ void flagK() {
    int b = blockIdx.x * 256 + threadIdx.x;
    const float* e = &g_energy[(size_t)b * 17];
    float mx = e[0], mn = e[0], mnn = e[1];
    #pragma unroll
    for (int j = 1; j < 17; j++) {
        mx = fmaxf(mx, e[j]);
        mn = fminf(mn, e[j]);
        if (j >= 2) mnn = fminf(mnn, e[j]);
    }
    float T = 0.03f * (mx - mn);
    g_accov[b] = -1;
    if (fabsf(e[0] - mnn) < T) {
        int p = atomicAdd(&g_cnt, 1);
        g_list[p] = b;
    }
}

// ---------------------------------------------------------------------------
// fixup3: per flagged batch, exact fp32 recompute of e0 and negatives within
// 2T of the approx min; writes accuracy override only. (R13-proven)
// ---------------------------------------------------------------------------
__global__ void __launch_bounds__(256)
fixup3(const float* __restrict__ anchor, const float* __restrict__ positive,
       const float* __restrict__ negatives,
       const float* __restrict__ W1, const float* __restrict__ b1,
       const float* __restrict__ W2, const float* __restrict__ b2,
       const float* __restrict__ W3, const float* __restrict__ b3,
       const float* __restrict__ W4, const float* __restrict__ b4) {
    __shared__ float xv[256], yv[256], apart[256], h1[256], h2[128], h3[64];
    __shared__ int   sS[16], nS;
    __shared__ float eres[18];
    const int tid = threadIdx.x, lane = tid & 31, wid = tid >> 5;  // 8 warps
    const int ncase = g_cnt;

    for (int q = blockIdx.x; q < ncase; q += FIXGRID) {
        const int b = g_list[q];
        if (tid == 0) {
            const float* e = &g_energy[(size_t)b * 17];
            float mx = e[0], mn = e[0], mnn = e[1];
            #pragma unroll
            for (int j = 1; j < 17; j++) {
                mx = fmaxf(mx, e[j]);
                mn = fminf(mn, e[j]);
                if (j >= 2) mnn = fminf(mnn, e[j]);
            }
            float T = 0.03f * (mx - mn);
            int n = 0;
            #pragma unroll
            for (int j = 1; j < 17; j++)
                if (e[j] <= mnn + 2.0f * T) sS[n++] = j;
            nS = n;
        }
        xv[tid] = anchor[(size_t)b * 256 + tid];
        __syncthreads();

        for (int o = wid; o < 256; o += 8) {
            const float* w = W1 + (size_t)o * 512;
            float acc = 0.f;
            #pragma unroll
            for (int i = 0; i < 8; i++) acc += w[lane + 32 * i] * xv[lane + 32 * i];
            #pragma unroll
            for (int s = 16; s; s >>= 1) acc += __shfl_xor_sync(0xFFFFFFFFu, acc, s);
            if (lane == 0) apart[o] = acc + b1[o];
        }
        __syncthreads();

        const int ncand = nS + 1;
        for (int s = 0; s < ncand; s++) {
            int j = (s == 0) ? 0 : sS[s - 1];
            const float* ysrc = j ? negatives + ((size_t)(b * 16 + j - 1)) * 256
                                  : positive + (size_t)b * 256;
            yv[tid] = ysrc[tid];
            __syncthreads();

            for (int o = wid; o < 256; o += 8) {
                const float* w = W1 + (size_t)o * 512 + 256;
                float acc = 0.f;
                #pragma unroll
                for (int i = 0; i < 8; i++) acc += w[lane + 32 * i] * yv[lane + 32 * i];
                #pragma unroll
                for (int st = 16; st; st >>= 1) acc += __shfl_xor_sync(0xFFFFFFFFu, acc, st);
                if (lane == 0) h1[o] = gelu_exact(apart[o] + acc);
            }
            __syncthreads();

            for (int o = wid; o < 128; o += 8) {
                const float* w = W2 + (size_t)o * 256;
                float acc = 0.f;
                #pragma unroll
                for (int i = 0; i < 8; i++) acc += w[lane + 32 * i] * h1[lane + 32 * i];
                #pragma unroll
                for (int st = 16; st; st >>= 1) acc += __shfl_xor_sync(0xFFFFFFFFu, acc, st);
                if (lane == 0) h2[o] = gelu_exact(acc + b2[o]);
            }
            __syncthreads();

            for (int o = wid; o < 64; o += 8) {
                const float* w = W3 + (size_t)o * 128;
                float acc = 0.f;
                #pragma unroll
                for (int i = 0; i < 4; i++) acc += w[lane + 32 * i] * h2[lane + 32 * i];
                #pragma unroll
                for (int st = 16; st; st >>= 1) acc += __shfl_xor_sync(0xFFFFFFFFu, acc, st);
                if (lane == 0) h3[o] = gelu_exact(acc + b3[o]) * W4[o];
            }
            __syncthreads();

            if (wid == 0) {
                float acc = h3[lane] + h3[lane + 32];
                #pragma unroll
                for (int st = 16; st; st >>= 1) acc += __shfl_xor_sync(0xFFFFFFFFu, acc, st);
                if (lane == 0) eres[s] = acc + b4[0];
            }
            __syncthreads();
        }

        if (tid == 0) {
            float emin = eres[1];
            for (int s = 2; s < ncand; s++) emin = fminf(emin, eres[s]);
            g_accov[b] = (eres[0] <= emin) ? 1 : 0;
        }
        __syncthreads();
    }
}

// ---------------------------------------------------------------------------
// reductions (reduce1 consumes the accuracy override)
// ---------------------------------------------------------------------------
__global__ void reduce1() {
    __shared__ float sl[256], sp[256], sn[256], sa[256];
    const int t = threadIdx.x;
    const int b = blockIdx.x * 256 + t;
    const float* e = &g_energy[(size_t)b * 17];

    float v[17];
    #pragma unroll
    for (int j = 0; j < 17; j++) v[j] = e[j];

    float l0 = -v[0] * TEMP_INV;
    float mx = l0;
    #pragma unroll
    for (int j = 1; j < 17; j++) mx = fmaxf(mx, -v[j] * TEMP_INV);
    float s = 0.f;
    #pragma unroll
    for (int j = 0; j < 17; j++) s += expf(-v[j] * TEMP_INV - mx);
    float loss = mx + logf(s) - l0;

    float pos = v[0], neg = 0.f, ok = 1.f;
    #pragma unroll
    for (int j = 1; j < 17; j++) {
        neg += v[j];
        if (v[j] < v[0]) ok = 0.f;
    }
    int ov = g_accov[b];
    if (ov >= 0) ok = (float)ov;

    sl[t] = loss; sp[t] = pos; sn[t] = neg; sa[t] = ok;
    __syncthreads();
    for (int st = 128; st > 0; st >>= 1) {
        if (t < st) {
            sl[t] += sl[t + st]; sp[t] += sp[t + st];
            sn[t] += sn[t + st]; sa[t] += sa[t + st];
        }
        __syncthreads();
    }
    if (t == 0) {
        g_part[blockIdx.x][0] = sl[0];
        g_part[blockIdx.x][1] = sp[0];
        g_part[blockIdx.x][2] = sn[0];
        g_part[blockIdx.x][3] = sa[0];
    }
}

__global__ void reduce2(float* __restrict__ out) {
    __shared__ float s[128][4];
    const int t = threadIdx.x;
    #pragma unroll
    for (int c = 0; c < 4; c++) s[t][c] = g_part[t][c];
    __syncthreads();
    for (int st = 64; st > 0; st >>= 1) {
        if (t < st) {
            #pragma unroll
            for (int c = 0; c < 4; c++) s[t][c] += s[t + st][c];
        }
        __syncthreads();
    }
    if (t == 0) {
        out[0] = s[0][0] / 32768.0f;
        out[1] = s[0][1] / 32768.0f;
        out[2] = s[0][2] / (32768.0f * 16.0f);
        out[3] = s[0][3] / 32768.0f;
    }
}

// ---------------------------------------------------------------------------
extern "C" void kernel_launch(void* const* d_in, const int* in_sizes, int n_in,
                              void* d_out, int out_size) {
    const float* anchor    = (const float*)d_in[0];
    const float* positive  = (const float*)d_in[1];
    const float* negatives = (const float*)d_in[2];
    const float* W1 = (const float*)d_in[3];
    const float* b1 = (const float*)d_in[4];
    const float* W2 = (const float*)d_in[5];
    const float* b2 = (const float*)d_in[6];
    const float* W3 = (const float*)d_in[7];
    const float* b3 = (const float*)d_in[8];
    const float* W4 = (const float*)d_in[9];
    const float* b4 = (const float*)d_in[10];
    float* out = (float*)d_out;

    cudaFuncSetAttribute(mmaA,    cudaFuncAttributeMaxDynamicSharedMemorySize, SMEM_A);
    cudaFuncSetAttribute(energyT, cudaFuncAttributeMaxDynamicSharedMemorySize, SMEM_EN);

    prepW_a<<<512, 256>>>(W1);                                      // 1 (zeros g_cnt)
    prepW_b<<<160, 256>>>(W2, W3);                                  // 2
    mmaA<<<NB / 128, 256, SMEM_A>>>(anchor, b1);                    // 3
    energyT<<<NBLK, 256, SMEM_EN>>>(positive, negatives, b2, b3, W4, b4); // 4 (profiled)
    flagK<<<NB / 256, 256>>>();                                     // 5
    fixup3<<<FIXGRID, 256>>>(anchor, positive, negatives,
                             W1, b1, W2, b2, W3, b3, W4, b4);       // 6
    reduce1<<<128, 256>>>();                                        // 7
    reduce2<<<1, 128>>>(out);                                       // 8
}